// round 2
// baseline (speedup 1.0000x reference)
#include <cuda_runtime.h>
#include <math.h>

#define NI 128
#define RR 36
#define WW 50
#define DD 1024
#define MM (NI*RR)      // 4608
#define NN (NI*WW)      // 6400

// Scratch (device globals — allocation-free rule)
__device__ float g_attn[MM * NN];       // attn[(i*RR+r)*NN + (c*WW+w)]
__device__ float g_gram[NI * RR * RR];  // G[i][r1][r2]
__device__ float g_w1[NI * WW];         // |s[c,w]|
__device__ float g_scores[NI * NI];     // scores[i][c]

// ---------------------------------------------------------------------------
// Kernel A: attn_raw = im_flat (4608x1024) * s_flat^T (6400x1024)  [NT GEMM]
// ---------------------------------------------------------------------------
#define BM 128
#define BN 128
#define BK 8
#define TM 8
#define TN 8

__global__ __launch_bounds__(256) void sgemm_nt(const float* __restrict__ A,
                                                const float* __restrict__ B) {
    __shared__ float As[BK][BM];
    __shared__ float Bs[BK][BN];
    const int bm = blockIdx.y * BM;
    const int bn = blockIdx.x * BN;
    const int tid = threadIdx.x;
    const int tx = tid & 15;        // 0..15
    const int ty = tid >> 4;        // 0..15
    const int lrow = tid >> 1;      // 0..127
    const int lk4  = (tid & 1) * 4; // 0 or 4

    float acc[TM][TN];
    #pragma unroll
    for (int i = 0; i < TM; i++)
        #pragma unroll
        for (int j = 0; j < TN; j++) acc[i][j] = 0.f;

    const float* Aptr = A + (bm + lrow) * DD + lk4;
    const float* Bptr = B + (bn + lrow) * DD + lk4;

    for (int k0 = 0; k0 < DD; k0 += BK) {
        float4 av = *(const float4*)(Aptr + k0);
        float4 bv = *(const float4*)(Bptr + k0);
        As[lk4 + 0][lrow] = av.x; As[lk4 + 1][lrow] = av.y;
        As[lk4 + 2][lrow] = av.z; As[lk4 + 3][lrow] = av.w;
        Bs[lk4 + 0][lrow] = bv.x; Bs[lk4 + 1][lrow] = bv.y;
        Bs[lk4 + 2][lrow] = bv.z; Bs[lk4 + 3][lrow] = bv.w;
        __syncthreads();
        #pragma unroll
        for (int k = 0; k < BK; k++) {
            float a[TM], b[TN];
            #pragma unroll
            for (int i = 0; i < TM; i++) a[i] = As[k][ty * TM + i];
            #pragma unroll
            for (int j = 0; j < TN; j++) b[j] = Bs[k][tx * TN + j];
            #pragma unroll
            for (int i = 0; i < TM; i++)
                #pragma unroll
                for (int j = 0; j < TN; j++) acc[i][j] += a[i] * b[j];
        }
        __syncthreads();
    }

    #pragma unroll
    for (int i = 0; i < TM; i++) {
        const int m = bm + ty * TM + i;
        #pragma unroll
        for (int j = 0; j < TN; j++) {
            const int n = bn + tx * TN + j;
            g_attn[m * NN + n] = acc[i][j];
        }
    }
}

// ---------------------------------------------------------------------------
// Kernel B: per-image Gram matrix G[i] = im[i] * im[i]^T  (36x36, K=1024)
// ---------------------------------------------------------------------------
__global__ __launch_bounds__(256) void gram_kernel(const float* __restrict__ im) {
    __shared__ float sIm[RR][130];  // 128-wide chunk, padded
    const int i = blockIdx.x;
    const int tid = threadIdx.x;
    const int PAIRS = RR * RR;      // 1296
    float acc[6] = {0.f, 0.f, 0.f, 0.f, 0.f, 0.f};

    for (int d0 = 0; d0 < DD; d0 += 128) {
        for (int idx = tid; idx < RR * 128; idx += 256) {
            int r = idx >> 7, k = idx & 127;
            sIm[r][k] = im[(i * RR + r) * DD + d0 + k];
        }
        __syncthreads();
        #pragma unroll
        for (int p = 0; p < 6; p++) {
            int pair = tid + p * 256;
            if (pair < PAIRS) {
                int r1 = pair / RR, r2 = pair % RR;
                float sum = 0.f;
                for (int k = 0; k < 128; k++) sum += sIm[r1][k] * sIm[r2][k];
                acc[p] += sum;
            }
        }
        __syncthreads();
    }
    #pragma unroll
    for (int p = 0; p < 6; p++) {
        int pair = tid + p * 256;
        if (pair < PAIRS) g_gram[i * PAIRS + pair] = acc[p];
    }
}

// ---------------------------------------------------------------------------
// Kernel W1: caption word norms |s[c,w]| — one warp per row
// ---------------------------------------------------------------------------
__global__ __launch_bounds__(256) void w1_kernel(const float* __restrict__ s) {
    const int row = blockIdx.x * 8 + (threadIdx.x >> 5);
    const int lane = threadIdx.x & 31;
    if (row < NI * WW) {
        const float* p = s + row * DD;
        float sum = 0.f;
        for (int k = lane; k < DD; k += 32) { float v = p[k]; sum += v * v; }
        #pragma unroll
        for (int off = 16; off; off >>= 1) sum += __shfl_xor_sync(0xFFFFFFFFu, sum, off);
        if (lane == 0) g_w1[row] = sqrtf(sum);
    }
}

// ---------------------------------------------------------------------------
// Kernel C: per (c,i) pair — leaky/mask/l2norm, softmax over r, w12 & w2 via
// Gram quadratic form, LSE over valid words -> scores[i][c]
// ---------------------------------------------------------------------------
__global__ __launch_bounds__(128) void pair_kernel(const int* __restrict__ s_l) {
    __shared__ float rawS[RR][WW];
    __shared__ float aS[RR][WW];
    __shared__ float tS[WW][RR + 1];
    __shared__ float gS[RR][RR + 1];
    __shared__ float red[WW];

    const int c = blockIdx.x, i = blockIdx.y;
    const int tid = threadIdx.x;
    const int len = s_l[c];

    // load the 36x50 raw block (rows stride NN in the big attn matrix)
    for (int idx = tid; idx < RR * WW; idx += 128) {
        int r = idx / WW, w = idx % WW;
        rawS[r][w] = g_attn[(i * RR + r) * NN + c * WW + w];
    }
    // load Gram
    for (int idx = tid; idx < RR * RR; idx += 128) {
        gS[idx / RR][idx % RR] = g_gram[i * RR * RR + idx];
    }
    __syncthreads();

    // step 1: per-region row — leaky_relu(0.1), word mask, L2-normalize over w
    if (tid < RR) {
        const int r = tid;
        float ss = 0.f;
        for (int w = 0; w < WW; w++) {
            float v = rawS[r][w];
            v = (v > 0.f) ? v : 0.1f * v;
            v = (w < len) ? v : 0.f;
            ss += v * v;
            aS[r][w] = v;
        }
        float inv = 1.f / (sqrtf(ss) + 1e-8f);
        for (int w = 0; w < WW; w++) aS[r][w] *= inv;
    }
    __syncthreads();

    // step 2: per-word — softmax over r (lambda=9), w12, w2 via Gram, row_sim, exp
    if (tid < WW) {
        const int w = tid;
        float mx = -1e30f;
        for (int r = 0; r < RR; r++) mx = fmaxf(mx, aS[r][w]);
        float ssum = 0.f;
        for (int r = 0; r < RR; r++) {
            float e = expf(9.f * (aS[r][w] - mx));
            tS[w][r] = e;
            ssum += e;
        }
        const float inv = 1.f / ssum;
        float w12 = 0.f;
        for (int r = 0; r < RR; r++) {
            float t = tS[w][r] * inv;
            tS[w][r] = t;
            w12 += t * rawS[r][w];
        }
        float w2sq = 0.f;
        for (int r = 0; r < RR; r++) {
            float t = tS[w][r];
            float dot = 0.f;
            for (int r2 = 0; r2 < RR; r2++) dot += tS[w][r2] * gS[r][r2];
            w2sq += t * dot;
        }
        const float w2 = sqrtf(w2sq);
        const float w1v = g_w1[c * WW + w];
        const float denom = fmaxf(w1v * w2, 1e-8f);
        const float sim = w12 / denom;
        red[w] = (w < len) ? expf(6.f * sim) : 0.f;
    }
    __syncthreads();

    if (tid == 0) {
        float sum = 0.f;
        for (int w = 0; w < WW; w++) sum += red[w];
        g_scores[i * NI + c] = logf(sum) / 6.f;  // scores = sims.T
    }
}

// ---------------------------------------------------------------------------
// Kernel D: hinge loss with hardest negatives
// ---------------------------------------------------------------------------
__global__ __launch_bounds__(128) void loss_kernel(float* __restrict__ out) {
    __shared__ float diag[NI];
    __shared__ float partial[NI];
    const int t = threadIdx.x;
    diag[t] = g_scores[t * NI + t];
    __syncthreads();
    const float dt = diag[t];
    float m1 = 0.f, m2 = 0.f;
    for (int c = 0; c < NI; c++) {
        if (c != t) {
            float v = 0.2f + g_scores[t * NI + c] - dt;  // cost_s, row t
            m1 = fmaxf(m1, fmaxf(v, 0.f));
            float u = 0.2f + g_scores[c * NI + t] - dt;  // cost_im, col t
            m2 = fmaxf(m2, fmaxf(u, 0.f));
        }
    }
    partial[t] = m1 + m2;
    __syncthreads();
    if (t == 0) {
        float s = 0.f;
        for (int k = 0; k < NI; k++) s += partial[k];
        out[0] = s;
    }
}

// ---------------------------------------------------------------------------
extern "C" void kernel_launch(void* const* d_in, const int* in_sizes, int n_in,
                              void* d_out, int out_size) {
    const float* im  = (const float*)d_in[0];   // (128, 36, 1024) f32
    const float* s   = (const float*)d_in[1];   // (128, 50, 1024) f32
    const int*   s_l = (const int*)d_in[2];     // (128,) i32
    float* out = (float*)d_out;

    sgemm_nt<<<dim3(NN / BN, MM / BM), 256>>>(im, s);
    gram_kernel<<<NI, 256>>>(im);
    w1_kernel<<<(NI * WW + 7) / 8, 256>>>(s);
    pair_kernel<<<dim3(NI, NI), 128>>>(s_l);
    loss_kernel<<<1, 128>>>(out);
}

// round 10
// speedup vs baseline: 1.6753x; 1.6753x over previous
#include <cuda_runtime.h>
#include <cuda_bf16.h>
#include <cstdint>
#include <math.h>

#define NI 128
#define RR 36
#define WW 50
#define DD 1024
#define MM (NI*RR)      // 4608
#define NN (NI*WW)      // 6400
#define K3 3072
#define BK 32
#define KSTEPS (K3/BK)  // 96

// ---------------- device scratch (allocation-free rule) ----------------
// NOTE: these symbols are referenced ONLY from device code. Passing them as
// kernel arguments from host code is UB (host shadow address) and on GB300
// silently writes to host memory via ATS — that was the R4/R9 bug.
__device__ float         g_attn[(size_t)MM * NN];   // 118 MB fp32
__device__ __nv_bfloat16 g_abf[(size_t)MM * K3];    // 28 MB  [hi|hi|lo]
__device__ __nv_bfloat16 g_bbf[(size_t)NN * K3];    // 39 MB  [hi|lo|hi]
__device__ float         g_gram[NI * RR * RR];
__device__ float         g_w1[NI * WW];
__device__ float         g_scores[NI * NI];

// ---------------- baseline-ISA PTX helpers ----------------
__device__ __forceinline__ uint32_t smem_u32(const void* p) {
    uint32_t a;
    asm("{ .reg .u64 t; cvta.to.shared.u64 t, %1; cvt.u32.u64 %0, t; }" : "=r"(a) : "l"(p));
    return a;
}
#define CP_ASYNC_16(dst_u32, src_ptr) \
    asm volatile("cp.async.cg.shared.global [%0], [%1], 16;" :: "r"(dst_u32), "l"(src_ptr))
#define CP_COMMIT()  asm volatile("cp.async.commit_group;" ::: "memory")
#define CP_WAIT(n)   asm volatile("cp.async.wait_group %0;" :: "n"(n) : "memory")

#define MMA_BF16(c, a0, a1, a2, a3, b0, b1) \
    asm volatile("mma.sync.aligned.m16n8k16.row.col.f32.bf16.bf16.f32 " \
        "{%0,%1,%2,%3}, {%4,%5,%6,%7}, {%8,%9}, {%0,%1,%2,%3};" \
        : "+f"((c)[0]), "+f"((c)[1]), "+f"((c)[2]), "+f"((c)[3]) \
        : "r"(a0), "r"(a1), "r"(a2), "r"(a3), "r"(b0), "r"(b1))

// ---------------------------------------------------------------------------
// Convert: fp32 -> bf16 hi/lo split, K'=3072 layout. Destination selected
// INSIDE the kernel (device-side symbol reference — never passed from host).
//   mode 0 (A -> g_abf): [0,1024)=hi  [1024,2048)=hi  [2048,3072)=lo
//   mode 1 (B -> g_bbf): [0,1024)=hi  [1024,2048)=lo  [2048,3072)=hi
// ---------------------------------------------------------------------------
template <int MODE>
__global__ __launch_bounds__(256) void convert_split(const float* __restrict__ src) {
    __nv_bfloat16* __restrict__ dst = (MODE == 0) ? g_abf : g_bbf;
    const size_t idx4 = ((size_t)blockIdx.x * 256 + threadIdx.x) * 4;
    const int m = (int)(idx4 / DD);
    const int k = (int)(idx4 % DD);
    float4 v = *(const float4*)(src + idx4);
    union { __nv_bfloat162 b2[2]; uint2 u; } hv, lv;
    __nv_bfloat16 h0 = __float2bfloat16(v.x);
    __nv_bfloat16 h1 = __float2bfloat16(v.y);
    __nv_bfloat16 h2 = __float2bfloat16(v.z);
    __nv_bfloat16 h3 = __float2bfloat16(v.w);
    hv.b2[0] = __nv_bfloat162(h0, h1);
    hv.b2[1] = __nv_bfloat162(h2, h3);
    lv.b2[0] = __nv_bfloat162(__float2bfloat16(v.x - __bfloat162float(h0)),
                              __float2bfloat16(v.y - __bfloat162float(h1)));
    lv.b2[1] = __nv_bfloat162(__float2bfloat16(v.z - __bfloat162float(h2)),
                              __float2bfloat16(v.w - __bfloat162float(h3)));
    __nv_bfloat16* base = dst + (size_t)m * K3 + k;
    *(uint2*)(base)        = hv.u;
    *(uint2*)(base + 1024) = (MODE == 0) ? hv.u : lv.u;
    *(uint2*)(base + 2048) = (MODE == 0) ? lv.u : hv.u;
}

// ---------------------------------------------------------------------------
// mma.sync bf16 NT GEMM: g_attn[4608 x 6400] = A'[4608 x 3072] * B'[6400 x 3072]^T
// 128x128 tile, 256 thr (8 warps = 4m x 2n, 32x64 each), BK=32, 3-stage cp.async.
// Fragments fed by explicit per-thread 4-byte smem loads.
// ---------------------------------------------------------------------------
#define ROWB 80                       // padded row stride in bytes (40 bf16)
#define STAGE_BYTES (2 * 128 * ROWB)  // 20480
#define GEMM_SMEM (3 * STAGE_BYTES)   // 61440

__device__ __forceinline__ void load_stage(uint32_t sbase, int slot,
                                           const __nv_bfloat16* __restrict__ Arow,
                                           const __nv_bfloat16* __restrict__ Brow,
                                           int k0, int tid) {
    const uint32_t st = sbase + slot * STAGE_BYTES;
    #pragma unroll
    for (int h = 0; h < 2; h++) {
        const int c = tid + h * 256;
        const int row = c >> 2;          // 0..127
        const int seg = c & 3;           // 0..3 (16B each)
        const __nv_bfloat16* ga = Arow + (size_t)row * K3 + k0 + seg * 8;
        const __nv_bfloat16* gb = Brow + (size_t)row * K3 + k0 + seg * 8;
        CP_ASYNC_16(st + row * ROWB + seg * 16, ga);
        CP_ASYNC_16(st + 128 * ROWB + row * ROWB + seg * 16, gb);
    }
}

__global__ __launch_bounds__(256) void gemm_mma_bf16() {
    extern __shared__ char smem[];
    const uint32_t sbase = smem_u32(smem);
    const int tid = threadIdx.x;
    const int wid = tid >> 5;
    const int lane = tid & 31;
    const int warp_m = wid & 3;          // rows 32*warp_m
    const int warp_n = wid >> 2;         // cols 64*warp_n
    const int bm = blockIdx.y * 128;
    const int bn = blockIdx.x * 128;
    const int tg = lane >> 2;            // 0..7
    const int t4 = lane & 3;             // 0..3

    const __nv_bfloat16* Arow = g_abf + (size_t)bm * K3;
    const __nv_bfloat16* Brow = g_bbf + (size_t)bn * K3;

    float acc[2][8][4];
    #pragma unroll
    for (int i = 0; i < 2; i++)
        #pragma unroll
        for (int j = 0; j < 8; j++)
            #pragma unroll
            for (int q = 0; q < 4; q++) acc[i][j][q] = 0.f;

    // A frag: a0 = {A[m][k],A[m][k+1]}, m = warp_m*32 + tg (+8/+16/+24), k = 2*t4 (+8)
    const uint32_t aoff = (uint32_t)((warp_m * 32 + tg) * ROWB + t4 * 4);
    // B frag ([n][k] storage): b0 = {B[k][n],B[k+1][n]}, n = warp_n*64 + tg, k = 2*t4 (+8)
    const uint32_t boff = (uint32_t)(128 * ROWB + (warp_n * 64 + tg) * ROWB + t4 * 4);

    load_stage(sbase, 0, Arow, Brow, 0, tid);  CP_COMMIT();
    load_stage(sbase, 1, Arow, Brow, BK, tid); CP_COMMIT();

    int slot = 0;
    for (int t = 0; t < KSTEPS; t++) {
        CP_WAIT(1);
        __syncthreads();
        if (t + 2 < KSTEPS)
            load_stage(sbase, (slot + 2) % 3, Arow, Brow, (t + 2) * BK, tid);
        CP_COMMIT();

        const char* st = smem + slot * STAGE_BYTES;
        #pragma unroll
        for (int kk = 0; kk < 2; kk++) {       // two k16 halves of BK=32
            uint32_t a[2][4];
            uint32_t b[4][4];
            #pragma unroll
            for (int mi = 0; mi < 2; mi++) {
                const char* pa = st + aoff + mi * 16 * ROWB + kk * 32;
                a[mi][0] = *(const uint32_t*)(pa);
                a[mi][1] = *(const uint32_t*)(pa + 8 * ROWB);
                a[mi][2] = *(const uint32_t*)(pa + 16);
                a[mi][3] = *(const uint32_t*)(pa + 8 * ROWB + 16);
            }
            #pragma unroll
            for (int j = 0; j < 4; j++) {
                const char* pb = st + boff + j * 16 * ROWB + kk * 32;
                b[j][0] = *(const uint32_t*)(pb);                 // n-tile 2j,   k 0-7
                b[j][1] = *(const uint32_t*)(pb + 16);            // n-tile 2j,   k 8-15
                b[j][2] = *(const uint32_t*)(pb + 8 * ROWB);      // n-tile 2j+1, k 0-7
                b[j][3] = *(const uint32_t*)(pb + 8 * ROWB + 16); // n-tile 2j+1, k 8-15
            }
            #pragma unroll
            for (int mi = 0; mi < 2; mi++)
                #pragma unroll
                for (int j = 0; j < 4; j++) {
                    MMA_BF16(acc[mi][2 * j],     a[mi][0], a[mi][1], a[mi][2], a[mi][3],
                             b[j][0], b[j][1]);
                    MMA_BF16(acc[mi][2 * j + 1], a[mi][0], a[mi][1], a[mi][2], a[mi][3],
                             b[j][2], b[j][3]);
                }
        }
        slot = (slot + 1) % 3;
        __syncthreads();
    }

    // epilogue: C frag m16n8: thread holds (row tg + {0,8}, col t4*2 + {0,1})
    const int r0 = bm + warp_m * 32 + tg;
    const int c0 = bn + warp_n * 64 + t4 * 2;
    #pragma unroll
    for (int mi = 0; mi < 2; mi++) {
        #pragma unroll
        for (int j = 0; j < 8; j++) {
            float* p0 = g_attn + (size_t)(r0 + mi * 16) * NN + c0 + j * 8;
            float* p1 = g_attn + (size_t)(r0 + mi * 16 + 8) * NN + c0 + j * 8;
            *(float2*)p0 = make_float2(acc[mi][j][0], acc[mi][j][1]);
            *(float2*)p1 = make_float2(acc[mi][j][2], acc[mi][j][3]);
        }
    }
}

// ---------------------------------------------------------------------------
// Gram: G[i] = im[i] * im[i]^T  (36x36, K=1024)
// ---------------------------------------------------------------------------
__global__ __launch_bounds__(256) void gram_kernel(const float* __restrict__ im) {
    __shared__ float sIm[RR][130];
    const int i = blockIdx.x;
    const int tid = threadIdx.x;
    const int PAIRS = RR * RR;
    float acc[6] = {0.f, 0.f, 0.f, 0.f, 0.f, 0.f};

    for (int d0 = 0; d0 < DD; d0 += 128) {
        for (int idx = tid; idx < RR * 128; idx += 256) {
            int r = idx >> 7, k = idx & 127;
            sIm[r][k] = im[(i * RR + r) * DD + d0 + k];
        }
        __syncthreads();
        #pragma unroll
        for (int p = 0; p < 6; p++) {
            int pair = tid + p * 256;
            if (pair < PAIRS) {
                int r1 = pair / RR, r2 = pair % RR;
                float sum = 0.f;
                for (int k = 0; k < 128; k++) sum += sIm[r1][k] * sIm[r2][k];
                acc[p] += sum;
            }
        }
        __syncthreads();
    }
    #pragma unroll
    for (int p = 0; p < 6; p++) {
        int pair = tid + p * 256;
        if (pair < PAIRS) g_gram[i * PAIRS + pair] = acc[p];
    }
}

// ---------------------------------------------------------------------------
// |s[c,w]| — one warp per row
// ---------------------------------------------------------------------------
__global__ __launch_bounds__(256) void w1_kernel(const float* __restrict__ s) {
    const int row = blockIdx.x * 8 + (threadIdx.x >> 5);
    const int lane = threadIdx.x & 31;
    if (row < NI * WW) {
        const float* p = s + (size_t)row * DD;
        float sum = 0.f;
        for (int k = lane; k < DD; k += 32) { float v = p[k]; sum += v * v; }
        #pragma unroll
        for (int off = 16; off; off >>= 1) sum += __shfl_xor_sync(0xFFFFFFFFu, sum, off);
        if (lane == 0) g_w1[row] = sqrtf(sum);
    }
}

// ---------------------------------------------------------------------------
// Per (c,i) pair: leaky/mask/l2norm, softmax over r, w12 + w2 via Gram
// quadratic form (parallel U = t*G), LSE over valid words.
// ---------------------------------------------------------------------------
__global__ __launch_bounds__(128) void pair_kernel(const int* __restrict__ s_l) {
    __shared__ __align__(16) float rawS[RR][WW];
    __shared__ __align__(16) float aS[RR][WW];
    __shared__ __align__(16) float tS[WW][RR];
    __shared__ __align__(16) float gS[RR][RR];
    __shared__ __align__(16) float U[WW][RR];
    __shared__ float red[WW];
    __shared__ float w12s[WW];

    const int c = blockIdx.x, i = blockIdx.y;
    const int tid = threadIdx.x;
    const int len = s_l[c];

    for (int idx = tid; idx < RR * WW; idx += 128) {
        int r = idx / WW, w = idx % WW;
        rawS[r][w] = g_attn[(size_t)(i * RR + r) * NN + c * WW + w];
    }
    for (int idx = tid; idx < RR * RR; idx += 128)
        gS[idx / RR][idx % RR] = g_gram[i * RR * RR + idx];
    __syncthreads();

    // per-region: leaky_relu(0.1), word mask, L2-normalize over w
    if (tid < RR) {
        const int r = tid;
        float ss = 0.f;
        #pragma unroll 10
        for (int w = 0; w < WW; w++) {
            float v = rawS[r][w];
            v = (v > 0.f) ? v : 0.1f * v;
            v = (w < len) ? v : 0.f;
            ss += v * v;
            aS[r][w] = v;
        }
        float inv = 1.f / (sqrtf(ss) + 1e-8f);
        #pragma unroll 10
        for (int w = 0; w < WW; w++) aS[r][w] *= inv;
    }
    __syncthreads();

    // per-word: softmax over regions (lambda=9), and w12 = sum t * raw
    if (tid < WW) {
        const int w = tid;
        float mx = -1e30f;
        #pragma unroll
        for (int r = 0; r < RR; r++) mx = fmaxf(mx, aS[r][w]);
        float ssum = 0.f;
        #pragma unroll
        for (int r = 0; r < RR; r++) {
            float e = __expf(9.f * (aS[r][w] - mx));
            tS[w][r] = e;
            ssum += e;
        }
        const float inv = 1.f / ssum;
        float w12 = 0.f;
        #pragma unroll
        for (int r = 0; r < RR; r++) {
            float tv = tS[w][r] * inv;
            tS[w][r] = tv;
            w12 += tv * rawS[r][w];
        }
        w12s[w] = w12;
    }
    __syncthreads();

    // U[w][r0..r0+3] = sum_r2 t[w][r2] * G[r2][r0..r0+3]   (450 float4 items)
    for (int idx = tid; idx < WW * (RR / 4); idx += 128) {
        const int w = idx / (RR / 4);
        const int j = idx % (RR / 4);
        float4 acc = make_float4(0.f, 0.f, 0.f, 0.f);
        #pragma unroll
        for (int r2 = 0; r2 < RR; r2++) {
            const float tv = tS[w][r2];
            const float4 g4 = *(const float4*)&gS[r2][4 * j];
            acc.x += tv * g4.x; acc.y += tv * g4.y;
            acc.z += tv * g4.z; acc.w += tv * g4.w;
        }
        *(float4*)&U[w][4 * j] = acc;
    }
    __syncthreads();

    // per-word: w2^2 = t . U, similarity, masked exp
    if (tid < WW) {
        const int w = tid;
        float w2sq = 0.f;
        #pragma unroll
        for (int r = 0; r < RR; r++) w2sq += U[w][r] * tS[w][r];
        const float w2 = sqrtf(w2sq);
        const float w1v = g_w1[c * WW + w];
        const float denom = fmaxf(w1v * w2, 1e-8f);
        const float sim = w12s[w] / denom;
        red[w] = (w < len) ? expf(6.f * sim) : 0.f;
    }
    __syncthreads();

    if (tid == 0) {
        float sum = 0.f;
        #pragma unroll 10
        for (int w = 0; w < WW; w++) sum += red[w];
        g_scores[i * NI + c] = logf(sum) / 6.f;
    }
}

// ---------------------------------------------------------------------------
// Hinge loss with hardest negatives
// ---------------------------------------------------------------------------
__global__ __launch_bounds__(128) void loss_kernel(float* __restrict__ out) {
    __shared__ float diag[NI];
    __shared__ float partial[NI];
    const int t = threadIdx.x;
    diag[t] = g_scores[t * NI + t];
    __syncthreads();
    const float dt = diag[t];
    float m1 = 0.f, m2 = 0.f;
    for (int c = 0; c < NI; c++) {
        if (c != t) {
            float v = 0.2f + g_scores[t * NI + c] - dt;
            m1 = fmaxf(m1, fmaxf(v, 0.f));
            float u = 0.2f + g_scores[c * NI + t] - dt;
            m2 = fmaxf(m2, fmaxf(u, 0.f));
        }
    }
    partial[t] = m1 + m2;
    __syncthreads();
    if (t == 0) {
        float s = 0.f;
        for (int k = 0; k < NI; k++) s += partial[k];
        out[0] = s;
    }
}

// ---------------------------------------------------------------------------
extern "C" void kernel_launch(void* const* d_in, const int* in_sizes, int n_in,
                              void* d_out, int out_size) {
    const float* im  = (const float*)d_in[0];   // (128, 36, 1024) f32
    const float* s   = (const float*)d_in[1];   // (128, 50, 1024) f32
    const int*   s_l = (const int*)d_in[2];     // (128,) i32
    float* out = (float*)d_out;

    cudaFuncSetAttribute(gemm_mma_bf16, cudaFuncAttributeMaxDynamicSharedMemorySize,
                         GEMM_SMEM);

    convert_split<0><<<MM * DD / (256 * 4), 256>>>(im);
    convert_split<1><<<NN * DD / (256 * 4), 256>>>(s);
    gemm_mma_bf16<<<dim3(NN / 128, MM / 128), 256, GEMM_SMEM>>>();
    gram_kernel<<<NI, 256>>>(im);
    w1_kernel<<<(NI * WW + 7) / 8, 256>>>(s);
    pair_kernel<<<dim3(NI, NI), 128>>>(s_l);
    loss_kernel<<<1, 128>>>(out);
}